// round 1
// baseline (speedup 1.0000x reference)
#include <cuda_runtime.h>
#include <math.h>

#define T_     256
#define B_     128
#define F_     1024
#define U_     512
#define G_     2048   // 4*U
#define CODES_ 1024

// Scratch (module-load allocations, permitted)
__device__ float g_xz[(size_t)T_ * B_ * G_];     // 256 MB: precomputed x@W_in + b
__device__ float g_hseq[(size_t)T_ * B_ * U_];   // 64 MB: h for every timestep
__device__ float g_h0[B_ * U_];                  // zero initial h
__device__ float g_c[B_ * U_];                   // cell state (in-place across steps)

// ---------------------------------------------------------------------------
// init: zero h0 and c every launch (deterministic)
// ---------------------------------------------------------------------------
__global__ void init_state_kernel() {
    int i = blockIdx.x * blockDim.x + threadIdx.x;
    if (i < B_ * U_) { g_h0[i] = 0.f; g_c[i] = 0.f; }
}

// ---------------------------------------------------------------------------
// GEMM 1: g_xz[M=T*B, N=G] = x[M, F] @ W_in[F, G] + b_lstm
// BM=128, BN=64, BK=16, 256 threads (16x16), 8x4 per thread
// ---------------------------------------------------------------------------
__global__ __launch_bounds__(256)
void gemm_xz_kernel(const float* __restrict__ A,     // x, [M, K]
                    const float* __restrict__ Bm,    // W_in, [K, N]
                    const float* __restrict__ bias)  // b_lstm [N]
{
    const int M_ = T_ * B_;  (void)M_;
    const int K  = F_;
    const int N  = G_;

    __shared__ float As[16][128 + 4];
    __shared__ float Bs[16][64];

    const int tx = threadIdx.x, ty = threadIdx.y;
    const int tid = ty * 16 + tx;
    const int row0 = blockIdx.y * 128;
    const int col0 = blockIdx.x * 64;

    float acc[8][4];
#pragma unroll
    for (int i = 0; i < 8; i++)
#pragma unroll
        for (int j = 0; j < 4; j++) acc[i][j] = 0.f;

    for (int k0 = 0; k0 < K; k0 += 16) {
        // A tile: 128 rows x 16 cols = 512 float4, 2 per thread
#pragma unroll
        for (int i = 0; i < 2; i++) {
            int e  = tid + i * 256;
            int r  = e >> 2;
            int c4 = (e & 3) << 2;
            float4 v = *reinterpret_cast<const float4*>(
                &A[(size_t)(row0 + r) * K + k0 + c4]);
            As[c4 + 0][r] = v.x; As[c4 + 1][r] = v.y;
            As[c4 + 2][r] = v.z; As[c4 + 3][r] = v.w;
        }
        // B tile: 16 rows x 64 cols = 256 float4, 1 per thread
        {
            int r  = tid >> 4;
            int c4 = (tid & 15) << 2;
            float4 v = *reinterpret_cast<const float4*>(
                &Bm[(size_t)(k0 + r) * N + col0 + c4]);
            Bs[r][c4 + 0] = v.x; Bs[r][c4 + 1] = v.y;
            Bs[r][c4 + 2] = v.z; Bs[r][c4 + 3] = v.w;
        }
        __syncthreads();

#pragma unroll
        for (int kk = 0; kk < 16; kk++) {
            float a[8], b[4];
#pragma unroll
            for (int i = 0; i < 8; i++) a[i] = As[kk][i * 16 + ty];
#pragma unroll
            for (int j = 0; j < 4; j++) b[j] = Bs[kk][j * 16 + tx];
#pragma unroll
            for (int i = 0; i < 8; i++)
#pragma unroll
                for (int j = 0; j < 4; j++) acc[i][j] += a[i] * b[j];
        }
        __syncthreads();
    }

#pragma unroll
    for (int i = 0; i < 8; i++) {
        int row = row0 + i * 16 + ty;
#pragma unroll
        for (int j = 0; j < 4; j++) {
            int col = col0 + j * 16 + tx;
            g_xz[(size_t)row * N + col] = acc[i][j] + bias[col];
        }
    }
}

// ---------------------------------------------------------------------------
// LSTM step t: z = xz[t] + h_prev @ W_rec; gates; update c, h
// block = 32 units x 32 batch (all 4 gates), grid (U/32=16, B/32=4)
// h chained through g_hseq (prev timestep slice is read-only for this step)
// ---------------------------------------------------------------------------
__global__ __launch_bounds__(256)
void lstm_step_kernel(int t, const float* __restrict__ W_rec)
{
    __shared__ float Hs[32][17];        // [batch][k]
    __shared__ float Ws[16][4][32];     // [k][gate][unit]

    const int tx = threadIdx.x, ty = threadIdx.y;
    const int tid = ty * 16 + tx;
    const int u_base = blockIdx.x * 32;
    const int b_base = blockIdx.y * 32;

    const float* h_prev = (t == 0) ? g_h0 : (g_hseq + (size_t)(t - 1) * B_ * U_);
    float* h_out = g_hseq + (size_t)t * B_ * U_;
    const float* xz_t = g_xz + (size_t)t * B_ * G_;

    float acc[4][2][2];
#pragma unroll
    for (int g = 0; g < 4; g++)
#pragma unroll
        for (int a = 0; a < 2; a++)
#pragma unroll
            for (int b = 0; b < 2; b++) acc[g][a][b] = 0.f;

    for (int k0 = 0; k0 < U_; k0 += 16) {
        // Hs: 32 batch x 16 k = 512 elems, 2 per thread
#pragma unroll
        for (int i = 0; i < 2; i++) {
            int e = tid + i * 256;
            int r = e >> 4, cc = e & 15;
            Hs[r][cc] = h_prev[(size_t)(b_base + r) * U_ + k0 + cc];
        }
        // Ws: 16 k x 4 gates x 32 units = 2048 elems, 8 per thread
#pragma unroll
        for (int i = 0; i < 8; i++) {
            int e   = tid + i * 256;
            int kk  = e >> 7;
            int rem = e & 127;
            int g   = rem >> 5;
            int uu  = rem & 31;
            Ws[kk][g][uu] = W_rec[(size_t)(k0 + kk) * G_ + g * U_ + u_base + uu];
        }
        __syncthreads();

#pragma unroll
        for (int kk = 0; kk < 16; kk++) {
            float h0v = Hs[ty][kk];
            float h1v = Hs[ty + 16][kk];
#pragma unroll
            for (int g = 0; g < 4; g++) {
                float w0 = Ws[kk][g][tx];
                float w1 = Ws[kk][g][tx + 16];
                acc[g][0][0] += h0v * w0;
                acc[g][0][1] += h0v * w1;
                acc[g][1][0] += h1v * w0;
                acc[g][1][1] += h1v * w1;
            }
        }
        __syncthreads();
    }

#pragma unroll
    for (int bi = 0; bi < 2; bi++) {
        int b = b_base + ty + bi * 16;
#pragma unroll
        for (int ui = 0; ui < 2; ui++) {
            int u = u_base + tx + ui * 16;
            size_t zb = (size_t)b * G_ + u;
            float zi = acc[0][bi][ui] + xz_t[zb + 0 * U_];
            float zf = acc[1][bi][ui] + xz_t[zb + 1 * U_];
            float zg = acc[2][bi][ui] + xz_t[zb + 2 * U_];
            float zo = acc[3][bi][ui] + xz_t[zb + 3 * U_];
            float ig = 1.f / (1.f + expf(-zi));
            float fg = 1.f / (1.f + expf(-zf));
            float gg = tanhf(zg);
            float og = 1.f / (1.f + expf(-zo));
            size_t cu = (size_t)b * U_ + u;
            float cn = fg * g_c[cu] + ig * gg;
            g_c[cu] = cn;
            h_out[cu] = og * tanhf(cn);
        }
    }
}

// ---------------------------------------------------------------------------
// GEMM 3: out[M=T*B, N=CODES] = relu(mask[row] * (hseq @ W_dense) + b_dense)
// (h*mask)@W == mask * (h@W) since mask is a per-row scalar
// ---------------------------------------------------------------------------
__global__ __launch_bounds__(256)
void gemm_dense_kernel(const float* __restrict__ Bm,   // W_dense [U, CODES]
                       const float* __restrict__ bias, // b_dense
                       const float* __restrict__ mask, // [T*B]
                       float* __restrict__ C)          // d_out
{
    const int K = U_;
    const int N = CODES_;

    __shared__ float As[16][128 + 4];
    __shared__ float Bs[16][64];

    const int tx = threadIdx.x, ty = threadIdx.y;
    const int tid = ty * 16 + tx;
    const int row0 = blockIdx.y * 128;
    const int col0 = blockIdx.x * 64;

    float acc[8][4];
#pragma unroll
    for (int i = 0; i < 8; i++)
#pragma unroll
        for (int j = 0; j < 4; j++) acc[i][j] = 0.f;

    for (int k0 = 0; k0 < K; k0 += 16) {
#pragma unroll
        for (int i = 0; i < 2; i++) {
            int e  = tid + i * 256;
            int r  = e >> 2;
            int c4 = (e & 3) << 2;
            float4 v = *reinterpret_cast<const float4*>(
                &g_hseq[(size_t)(row0 + r) * K + k0 + c4]);
            As[c4 + 0][r] = v.x; As[c4 + 1][r] = v.y;
            As[c4 + 2][r] = v.z; As[c4 + 3][r] = v.w;
        }
        {
            int r  = tid >> 4;
            int c4 = (tid & 15) << 2;
            float4 v = *reinterpret_cast<const float4*>(
                &Bm[(size_t)(k0 + r) * N + col0 + c4]);
            Bs[r][c4 + 0] = v.x; Bs[r][c4 + 1] = v.y;
            Bs[r][c4 + 2] = v.z; Bs[r][c4 + 3] = v.w;
        }
        __syncthreads();

#pragma unroll
        for (int kk = 0; kk < 16; kk++) {
            float a[8], b[4];
#pragma unroll
            for (int i = 0; i < 8; i++) a[i] = As[kk][i * 16 + ty];
#pragma unroll
            for (int j = 0; j < 4; j++) b[j] = Bs[kk][j * 16 + tx];
#pragma unroll
            for (int i = 0; i < 8; i++)
#pragma unroll
                for (int j = 0; j < 4; j++) acc[i][j] += a[i] * b[j];
        }
        __syncthreads();
    }

#pragma unroll
    for (int i = 0; i < 8; i++) {
        int row = row0 + i * 16 + ty;
        float mk = mask[row];
#pragma unroll
        for (int j = 0; j < 4; j++) {
            int col = col0 + j * 16 + tx;
            float v = acc[i][j] * mk + bias[col];
            C[(size_t)row * N + col] = fmaxf(v, 0.f);
        }
    }
}

// ---------------------------------------------------------------------------
// In-place row softmax over 1024 cols; one block (256 thr) per row
// ---------------------------------------------------------------------------
__global__ __launch_bounds__(256)
void softmax_kernel(float* __restrict__ out)
{
    __shared__ float red[256];
    const int row = blockIdx.x;
    const int tid = threadIdx.x;
    float* p = out + (size_t)row * CODES_;

    float v[4];
    float m = -1e30f;
#pragma unroll
    for (int i = 0; i < 4; i++) {
        v[i] = p[tid + i * 256];
        m = fmaxf(m, v[i]);
    }
    red[tid] = m;
    __syncthreads();
    for (int s = 128; s > 0; s >>= 1) {
        if (tid < s) red[tid] = fmaxf(red[tid], red[tid + s]);
        __syncthreads();
    }
    m = red[0];
    __syncthreads();

    float sum = 0.f;
#pragma unroll
    for (int i = 0; i < 4; i++) {
        v[i] = expf(v[i] - m);
        sum += v[i];
    }
    red[tid] = sum;
    __syncthreads();
    for (int s = 128; s > 0; s >>= 1) {
        if (tid < s) red[tid] += red[tid + s];
        __syncthreads();
    }
    float inv = 1.f / red[0];
#pragma unroll
    for (int i = 0; i < 4; i++) p[tid + i * 256] = v[i] * inv;
}

// ---------------------------------------------------------------------------
extern "C" void kernel_launch(void* const* d_in, const int* in_sizes, int n_in,
                              void* d_out, int out_size)
{
    const float* x       = (const float*)d_in[0];  // [T,B,F]
    const float* mask    = (const float*)d_in[1];  // [T,B]
    const float* W_in    = (const float*)d_in[2];  // [F,4U]
    const float* W_rec   = (const float*)d_in[3];  // [U,4U]
    const float* b_lstm  = (const float*)d_in[4];  // [4U]
    const float* W_dense = (const float*)d_in[5];  // [U,CODES]
    const float* b_dense = (const float*)d_in[6];  // [CODES]
    float* out = (float*)d_out;                    // [T,B,CODES]

    // zero h0 / c
    init_state_kernel<<<(B_ * U_ + 255) / 256, 256>>>();

    // xz = x @ W_in + b_lstm  (M=32768, N=2048, K=1024)
    {
        dim3 grid(G_ / 64, (T_ * B_) / 128);
        dim3 blk(16, 16);
        gemm_xz_kernel<<<grid, blk>>>(x, W_in, b_lstm);
    }

    // recurrence: 256 sequential steps
    {
        dim3 grid(U_ / 32, B_ / 32);
        dim3 blk(16, 16);
        for (int t = 0; t < T_; t++)
            lstm_step_kernel<<<grid, blk>>>(t, W_rec);
    }

    // dense + mask + relu  (M=32768, N=1024, K=512)
    {
        dim3 grid(CODES_ / 64, (T_ * B_) / 128);
        dim3 blk(16, 16);
        gemm_dense_kernel<<<grid, blk>>>(W_dense, b_dense, mask, out);
    }

    // softmax rows
    softmax_kernel<<<T_ * B_, 256>>>(out);
}

// round 2
// speedup vs baseline: 1.8360x; 1.8360x over previous
#include <cuda_runtime.h>
#include <math.h>

#define T_     256
#define B_     128
#define F_     1024
#define U_     512
#define G_     2048   // 4*U
#define CODES_ 1024
#define NBLK   128    // persistent blocks (<=148 SMs -> all co-resident)
#define UB     4      // units per persistent block (16 gate-cols)

// Scratch (module-scope device allocations, permitted)
__device__ float g_xz[(size_t)T_ * B_ * G_];     // [t][b][4U]
__device__ float g_hseq[(size_t)T_ * U_ * B_];   // [t][u][b]  (u-major!)
__device__ float g_h0[U_ * B_];                  // zeros
__device__ unsigned g_bar;                       // grid barrier counter

// ---------------------------------------------------------------------------
__global__ void init_kernel() {
    int i = blockIdx.x * blockDim.x + threadIdx.x;
    if (i < U_ * B_) g_h0[i] = 0.f;
    if (i == 0) g_bar = 0u;
}

// ---------------------------------------------------------------------------
// GEMM 1: g_xz[M=T*B, N=2048] = x[M,1024] @ W_in[1024,2048] + b_lstm
// BM=128, BN=128, BK=16, 256 threads, 8x8 register tile
// ---------------------------------------------------------------------------
__global__ __launch_bounds__(256)
void gemm_xz_kernel(const float* __restrict__ A,
                    const float* __restrict__ Bm,
                    const float* __restrict__ bias)
{
    __shared__ float As[16][132];   // k-major, +4 pad
    __shared__ float Bs[16][128];

    const int tid = threadIdx.x;
    const int tx = tid & 15, ty = tid >> 4;
    const int row0 = blockIdx.y * 128;
    const int col0 = blockIdx.x * 128;

    float acc[8][8];
#pragma unroll
    for (int i = 0; i < 8; i++)
#pragma unroll
        for (int j = 0; j < 8; j++) acc[i][j] = 0.f;

    float bv[8];
#pragma unroll
    for (int j = 0; j < 8; j++) bv[j] = bias[col0 + tx * 8 + j];

    for (int k0 = 0; k0 < F_; k0 += 16) {
#pragma unroll
        for (int r = 0; r < 2; r++) {
            int e = tid + r * 256;
            int m = e >> 2, k4 = (e & 3) << 2;
            float4 v = *reinterpret_cast<const float4*>(
                &A[(size_t)(row0 + m) * F_ + k0 + k4]);
            As[k4 + 0][m] = v.x; As[k4 + 1][m] = v.y;
            As[k4 + 2][m] = v.z; As[k4 + 3][m] = v.w;
        }
#pragma unroll
        for (int r = 0; r < 2; r++) {
            int e = tid + r * 256;
            int kk = e >> 5, n4 = (e & 31) << 2;
            *reinterpret_cast<float4*>(&Bs[kk][n4]) =
                *reinterpret_cast<const float4*>(
                    &Bm[(size_t)(k0 + kk) * G_ + col0 + n4]);
        }
        __syncthreads();

#pragma unroll
        for (int kk = 0; kk < 16; kk++) {
            float a[8], b[8];
            *reinterpret_cast<float4*>(&a[0]) = *reinterpret_cast<float4*>(&As[kk][ty * 8]);
            *reinterpret_cast<float4*>(&a[4]) = *reinterpret_cast<float4*>(&As[kk][ty * 8 + 4]);
            *reinterpret_cast<float4*>(&b[0]) = *reinterpret_cast<float4*>(&Bs[kk][tx * 8]);
            *reinterpret_cast<float4*>(&b[4]) = *reinterpret_cast<float4*>(&Bs[kk][tx * 8 + 4]);
#pragma unroll
            for (int i = 0; i < 8; i++)
#pragma unroll
                for (int j = 0; j < 8; j++) acc[i][j] += a[i] * b[j];
        }
        __syncthreads();
    }

#pragma unroll
    for (int i = 0; i < 8; i++) {
        size_t row = row0 + ty * 8 + i;
#pragma unroll
        for (int j4 = 0; j4 < 8; j4 += 4) {
            float4 v;
            v.x = acc[i][j4 + 0] + bv[j4 + 0];
            v.y = acc[i][j4 + 1] + bv[j4 + 1];
            v.z = acc[i][j4 + 2] + bv[j4 + 2];
            v.w = acc[i][j4 + 3] + bv[j4 + 3];
            *reinterpret_cast<float4*>(&g_xz[row * G_ + col0 + tx * 8 + j4]) = v;
        }
    }
}

// ---------------------------------------------------------------------------
// Persistent LSTM recurrence: one launch, 256 steps, software grid barrier.
// Block j owns units [j*4, j*4+4) -> 16 W_rec cols resident in SMEM.
// ---------------------------------------------------------------------------
__global__ __launch_bounds__(256)
void lstm_persistent_kernel(const float* __restrict__ W_rec)
{
    __shared__ float Ws[512 * 16];   // [k][c], c = gate*4 + ulocal   (32 KB)
    __shared__ float HZ[16 * 128];   // Hs chunk [kk][b] / z-buffer [c][b] (8 KB)
    __shared__ float cs[4 * 128];    // cell state [ulocal][b]        (2 KB)

    const int tid = threadIdx.x;
    const int ublk = blockIdx.x * UB;

    // Load W slice (once) and zero cell state
    for (int idx = tid; idx < 512 * 16; idx += 256) {
        int k = idx >> 4, c = idx & 15;
        Ws[idx] = W_rec[(size_t)k * G_ + (c >> 2) * U_ + ublk + (c & 3)];
    }
    for (int idx = tid; idx < 4 * 128; idx += 256) cs[idx] = 0.f;
    __syncthreads();

    const int cq = tid & 7;          // col pair
    const int bq = tid >> 3;         // batch quad
    const int b0 = bq * 4;
    const int c0 = cq * 2;

    const int e0kk = tid >> 5,         e0b4 = (tid & 31) << 2;
    const int e1kk = (tid + 256) >> 5, e1b4 = ((tid + 256) & 31) << 2;

    for (int t = 0; t < T_; t++) {
        const float* hp = (t == 0) ? g_h0 : (g_hseq + (size_t)(t - 1) * U_ * B_);

        float acc[4][2];
#pragma unroll
        for (int i = 0; i < 4; i++) { acc[i][0] = 0.f; acc[i][1] = 0.f; }

        // prefetch chunk 0
        float4 p0 = *reinterpret_cast<const float4*>(&hp[(size_t)e0kk * B_ + e0b4]);
        float4 p1 = *reinterpret_cast<const float4*>(&hp[(size_t)e1kk * B_ + e1b4]);

        for (int kc = 0; kc < U_ / 16; kc++) {
            __syncthreads();
            *reinterpret_cast<float4*>(&HZ[e0kk * 128 + e0b4]) = p0;
            *reinterpret_cast<float4*>(&HZ[e1kk * 128 + e1b4]) = p1;
            if (kc + 1 < U_ / 16) {
                const float* hq = hp + (size_t)(kc + 1) * 16 * B_;
                p0 = *reinterpret_cast<const float4*>(&hq[(size_t)e0kk * B_ + e0b4]);
                p1 = *reinterpret_cast<const float4*>(&hq[(size_t)e1kk * B_ + e1b4]);
            }
            __syncthreads();

            const float* wb = &Ws[(kc * 16) * 16];
#pragma unroll
            for (int kk = 0; kk < 16; kk++) {
                float w0 = wb[kk * 16 + c0];
                float w1 = wb[kk * 16 + c0 + 1];
                float h0 = HZ[kk * 128 + b0 + 0];
                float h1 = HZ[kk * 128 + b0 + 1];
                float h2 = HZ[kk * 128 + b0 + 2];
                float h3 = HZ[kk * 128 + b0 + 3];
                acc[0][0] += h0 * w0; acc[0][1] += h0 * w1;
                acc[1][0] += h1 * w0; acc[1][1] += h1 * w1;
                acc[2][0] += h2 * w0; acc[2][1] += h2 * w1;
                acc[3][0] += h3 * w0; acc[3][1] += h3 * w1;
            }
        }
        __syncthreads();
        // stash z into SMEM: HZ[c][b]
#pragma unroll
        for (int i = 0; i < 4; i++) {
            HZ[(c0 + 0) * 128 + b0 + i] = acc[i][0];
            HZ[(c0 + 1) * 128 + b0 + i] = acc[i][1];
        }
        __syncthreads();

        // gate epilogue: 2 (b, ulocal) pairs per thread
        const float* xz_t = g_xz + (size_t)t * B_ * G_;
        float* h_out = g_hseq + (size_t)t * U_ * B_;
#pragma unroll
        for (int r = 0; r < 2; r++) {
            int p = tid + r * 256;
            int b = p & 127, ul = p >> 7;
            size_t xb = (size_t)b * G_ + ublk + ul;
            float zi = HZ[(0 * 4 + ul) * 128 + b] + xz_t[xb + 0 * U_];
            float zf = HZ[(1 * 4 + ul) * 128 + b] + xz_t[xb + 1 * U_];
            float zg = HZ[(2 * 4 + ul) * 128 + b] + xz_t[xb + 2 * U_];
            float zo = HZ[(3 * 4 + ul) * 128 + b] + xz_t[xb + 3 * U_];
            float ig = 1.f / (1.f + __expf(-zi));
            float fg = 1.f / (1.f + __expf(-zf));
            float gg = 1.f - 2.f / (1.f + __expf(2.f * zg));     // tanh, no-NaN form
            float og = 1.f / (1.f + __expf(-zo));
            float cn = fg * cs[ul * 128 + b] + ig * gg;
            cs[ul * 128 + b] = cn;
            float th = 1.f - 2.f / (1.f + __expf(2.f * cn));
            h_out[(size_t)(ublk + ul) * B_ + b] = og * th;
        }

        // software grid barrier
        __threadfence();
        __syncthreads();
        if (tid == 0) {
            atomicAdd(&g_bar, 1u);
            unsigned tgt = (unsigned)(NBLK * (t + 1));
            while (*((volatile unsigned*)&g_bar) < tgt) { }
            __threadfence();
        }
        __syncthreads();
    }
}

// ---------------------------------------------------------------------------
// GEMM 3: out[m, CODES] = relu(mask[m] * (h @ W_dense) + b_dense)
// A read from g_hseq [t][u][b]: block row-tile = one t, rows = b.
// ---------------------------------------------------------------------------
__global__ __launch_bounds__(256)
void gemm_dense_kernel(const float* __restrict__ Bm,
                       const float* __restrict__ bias,
                       const float* __restrict__ mask,
                       float* __restrict__ C)
{
    __shared__ float As[16][128];
    __shared__ float Bs[16][128];

    const int tid = threadIdx.x;
    const int tx = tid & 15, ty = tid >> 4;
    const int tblk = blockIdx.y;              // time index
    const int col0 = blockIdx.x * 128;
    const float* Ablk = g_hseq + (size_t)tblk * U_ * B_;

    float acc[8][8];
#pragma unroll
    for (int i = 0; i < 8; i++)
#pragma unroll
        for (int j = 0; j < 8; j++) acc[i][j] = 0.f;

    float bv[8];
#pragma unroll
    for (int j = 0; j < 8; j++) bv[j] = bias[col0 + tx * 8 + j];

    for (int k0 = 0; k0 < U_; k0 += 16) {
#pragma unroll
        for (int r = 0; r < 2; r++) {
            int e = tid + r * 256;
            int kk = e >> 5, b4 = (e & 31) << 2;
            *reinterpret_cast<float4*>(&As[kk][b4]) =
                *reinterpret_cast<const float4*>(&Ablk[(size_t)(k0 + kk) * B_ + b4]);
        }
#pragma unroll
        for (int r = 0; r < 2; r++) {
            int e = tid + r * 256;
            int kk = e >> 5, n4 = (e & 31) << 2;
            *reinterpret_cast<float4*>(&Bs[kk][n4]) =
                *reinterpret_cast<const float4*>(
                    &Bm[(size_t)(k0 + kk) * CODES_ + col0 + n4]);
        }
        __syncthreads();

#pragma unroll
        for (int kk = 0; kk < 16; kk++) {
            float a[8], b[8];
            *reinterpret_cast<float4*>(&a[0]) = *reinterpret_cast<float4*>(&As[kk][ty * 8]);
            *reinterpret_cast<float4*>(&a[4]) = *reinterpret_cast<float4*>(&As[kk][ty * 8 + 4]);
            *reinterpret_cast<float4*>(&b[0]) = *reinterpret_cast<float4*>(&Bs[kk][tx * 8]);
            *reinterpret_cast<float4*>(&b[4]) = *reinterpret_cast<float4*>(&Bs[kk][tx * 8 + 4]);
#pragma unroll
            for (int i = 0; i < 8; i++)
#pragma unroll
                for (int j = 0; j < 8; j++) acc[i][j] += a[i] * b[j];
        }
        __syncthreads();
    }

#pragma unroll
    for (int i = 0; i < 8; i++) {
        int b = ty * 8 + i;
        size_t row = (size_t)tblk * 128 + b;
        float mk = mask[row];
#pragma unroll
        for (int j4 = 0; j4 < 8; j4 += 4) {
            float4 v;
            v.x = fmaxf(acc[i][j4 + 0] * mk + bv[j4 + 0], 0.f);
            v.y = fmaxf(acc[i][j4 + 1] * mk + bv[j4 + 1], 0.f);
            v.z = fmaxf(acc[i][j4 + 2] * mk + bv[j4 + 2], 0.f);
            v.w = fmaxf(acc[i][j4 + 3] * mk + bv[j4 + 3], 0.f);
            *reinterpret_cast<float4*>(&C[row * CODES_ + col0 + tx * 8 + j4]) = v;
        }
    }
}

// ---------------------------------------------------------------------------
// In-place row softmax over 1024 cols; one block (256 thr) per row
// ---------------------------------------------------------------------------
__global__ __launch_bounds__(256)
void softmax_kernel(float* __restrict__ out)
{
    __shared__ float red[256];
    const int row = blockIdx.x;
    const int tid = threadIdx.x;
    float* p = out + (size_t)row * CODES_;

    float v[4];
    float m = -1e30f;
#pragma unroll
    for (int i = 0; i < 4; i++) {
        v[i] = p[tid + i * 256];
        m = fmaxf(m, v[i]);
    }
    red[tid] = m;
    __syncthreads();
    for (int s = 128; s > 0; s >>= 1) {
        if (tid < s) red[tid] = fmaxf(red[tid], red[tid + s]);
        __syncthreads();
    }
    m = red[0];
    __syncthreads();

    float sum = 0.f;
#pragma unroll
    for (int i = 0; i < 4; i++) {
        v[i] = __expf(v[i] - m);
        sum += v[i];
    }
    red[tid] = sum;
    __syncthreads();
    for (int s = 128; s > 0; s >>= 1) {
        if (tid < s) red[tid] += red[tid + s];
        __syncthreads();
    }
    float inv = 1.f / red[0];
#pragma unroll
    for (int i = 0; i < 4; i++) p[tid + i * 256] = v[i] * inv;
}

// ---------------------------------------------------------------------------
extern "C" void kernel_launch(void* const* d_in, const int* in_sizes, int n_in,
                              void* d_out, int out_size)
{
    const float* x       = (const float*)d_in[0];  // [T,B,F]
    const float* mask    = (const float*)d_in[1];  // [T,B]
    const float* W_in    = (const float*)d_in[2];  // [F,4U]
    const float* W_rec   = (const float*)d_in[3];  // [U,4U]
    const float* b_lstm  = (const float*)d_in[4];  // [4U]
    const float* W_dense = (const float*)d_in[5];  // [U,CODES]
    const float* b_dense = (const float*)d_in[6];  // [CODES]
    float* out = (float*)d_out;                    // [T,B,CODES]

    init_kernel<<<(U_ * B_ + 255) / 256, 256>>>();

    {   // xz = x @ W_in + b   (M=32768, N=2048, K=1024)
        dim3 grid(G_ / 128, (T_ * B_) / 128);
        gemm_xz_kernel<<<grid, 256>>>(x, W_in, b_lstm);
    }

    // entire recurrence in ONE persistent launch
    lstm_persistent_kernel<<<NBLK, 256>>>(W_rec);

    {   // dense + mask + relu (M=32768, N=1024, K=512)
        dim3 grid(CODES_ / 128, T_);
        gemm_dense_kernel<<<grid, 256>>>(W_dense, b_dense, mask, out);
    }

    softmax_kernel<<<T_ * B_, 256>>>(out);
}

// round 3
// speedup vs baseline: 2.0555x; 1.1196x over previous
#include <cuda_runtime.h>
#include <math.h>
#include <stdint.h>

#define T_     256
#define B_     128
#define F_     1024
#define U_     512
#define G_     2048   // 4*U
#define CODES_ 1024
#define NBLK   128
#define UB     4
#define CHUNK  64     // K-chunk for LSTM h staging

// Scratch (module-scope device allocations, permitted)
__device__ float g_xz[(size_t)T_ * G_ * B_];     // [t][c][b]  c = gate*512+u  (TRANSPOSED)
__device__ float g_hseq[(size_t)T_ * U_ * B_];   // [t][u][b]
__device__ float g_h0[U_ * B_];
__device__ unsigned g_bar;

// ---------------------------------------------------------------------------
// f32x2 packed helpers (PTX-only path; sm_100a+)
// ---------------------------------------------------------------------------
__device__ __forceinline__ uint64_t splat2(float x) {
    uint64_t d; asm("mov.b64 %0, {%1, %1};" : "=l"(d) : "f"(x)); return d;
}
__device__ __forceinline__ void ffma2(uint64_t& d, uint64_t a, uint64_t b) {
    asm("fma.rn.f32x2 %0, %1, %2, %0;" : "+l"(d) : "l"(a), "l"(b));
}
__device__ __forceinline__ float2 unpack2(uint64_t d) {
    float2 r; asm("mov.b64 {%0, %1}, %2;" : "=f"(r.x), "=f"(r.y) : "l"(d)); return r;
}

// ---------------------------------------------------------------------------
__global__ void init_kernel() {
    int i = blockIdx.x * blockDim.x + threadIdx.x;
    if (i < U_ * B_) g_h0[i] = 0.f;
    if (i == 0) g_bar = 0u;
}

// ---------------------------------------------------------------------------
// GEMM 1: xz = x @ W_in + b_lstm, output TRANSPOSED to g_xz[t][col][b]
// BM=128 (one t), BN=128, BK=16, 256 thr, 8x8 reg tile, pack over rows (i)
// ---------------------------------------------------------------------------
__global__ __launch_bounds__(256)
void gemm_xz_kernel(const float* __restrict__ A,
                    const float* __restrict__ Bm,
                    const float* __restrict__ bias)
{
    __shared__ float As[16][132];
    __shared__ float Bs[16][128];

    const int tid = threadIdx.x;
    const int tx = tid & 15, ty = tid >> 4;
    const int t    = blockIdx.y;            // row tile == one timestep (128 rows)
    const int row0 = t * 128;
    const int col0 = blockIdx.x * 128;

    uint64_t acc[4][8];                     // [row-pair][col]
#pragma unroll
    for (int i = 0; i < 4; i++)
#pragma unroll
        for (int j = 0; j < 8; j++) acc[i][j] = 0ull;

    for (int k0 = 0; k0 < F_; k0 += 16) {
#pragma unroll
        for (int r = 0; r < 2; r++) {
            int e = tid + r * 256;
            int m = e >> 2, k4 = (e & 3) << 2;
            float4 v = *reinterpret_cast<const float4*>(
                &A[(size_t)(row0 + m) * F_ + k0 + k4]);
            As[k4 + 0][m] = v.x; As[k4 + 1][m] = v.y;
            As[k4 + 2][m] = v.z; As[k4 + 3][m] = v.w;
        }
#pragma unroll
        for (int r = 0; r < 2; r++) {
            int e = tid + r * 256;
            int kk = e >> 5, n4 = (e & 31) << 2;
            *reinterpret_cast<float4*>(&Bs[kk][n4]) =
                *reinterpret_cast<const float4*>(
                    &Bm[(size_t)(k0 + kk) * G_ + col0 + n4]);
        }
        __syncthreads();

#pragma unroll
        for (int kk = 0; kk < 16; kk++) {
            // row pairs: consecutive floats in As row -> already-packed u64
            uint64_t ap[4];
            ulonglong2 a01 = *reinterpret_cast<ulonglong2*>(&As[kk][ty * 8]);
            ulonglong2 a23 = *reinterpret_cast<ulonglong2*>(&As[kk][ty * 8 + 4]);
            ap[0] = a01.x; ap[1] = a01.y; ap[2] = a23.x; ap[3] = a23.y;
            float b[8];
            *reinterpret_cast<float4*>(&b[0]) = *reinterpret_cast<float4*>(&Bs[kk][tx * 8]);
            *reinterpret_cast<float4*>(&b[4]) = *reinterpret_cast<float4*>(&Bs[kk][tx * 8 + 4]);
#pragma unroll
            for (int j = 0; j < 8; j++) {
                uint64_t bs = splat2(b[j]);
                ffma2(acc[0][j], ap[0], bs);
                ffma2(acc[1][j], ap[1], bs);
                ffma2(acc[2][j], ap[2], bs);
                ffma2(acc[3][j], ap[3], bs);
            }
        }
        __syncthreads();
    }

    // transposed store: g_xz[t][col][b], column vector = unpacked row pairs
#pragma unroll
    for (int j = 0; j < 8; j++) {
        int col = col0 + tx * 8 + j;
        float bj = bias[col];
        float2 p0 = unpack2(acc[0][j]);
        float2 p1 = unpack2(acc[1][j]);
        float2 p2 = unpack2(acc[2][j]);
        float2 p3 = unpack2(acc[3][j]);
        float4 v0 = { p0.x + bj, p0.y + bj, p1.x + bj, p1.y + bj };
        float4 v1 = { p2.x + bj, p2.y + bj, p3.x + bj, p3.y + bj };
        size_t base = ((size_t)t * G_ + col) * B_ + ty * 8;
        *reinterpret_cast<float4*>(&g_xz[base])     = v0;
        *reinterpret_cast<float4*>(&g_xz[base + 4]) = v1;
    }
}

// ---------------------------------------------------------------------------
// Persistent LSTM: one launch, 256 steps, software grid barrier.
// Block owns 4 units (16 gate cols); W slice resident in SMEM; f32x2 math.
// Dynamic smem: Ws[512*16] | buf[2][CHUNK*128] | cs[4*128]
// ---------------------------------------------------------------------------
__global__ __launch_bounds__(256)
void lstm_persistent_kernel(const float* __restrict__ W_rec)
{
    extern __shared__ float sm[];
    float* Ws  = sm;                       // 8192 floats
    float* buf = sm + 512 * 16;            // 2 * CHUNK*128
    float* cs  = buf + 2 * CHUNK * 128;    // 512 floats

    const int tid  = threadIdx.x;
    const int ublk = blockIdx.x * UB;

    for (int idx = tid; idx < 512 * 16; idx += 256) {
        int k = idx >> 4, c = idx & 15;
        Ws[idx] = W_rec[(size_t)k * G_ + (c >> 2) * U_ + ublk + (c & 3)];
    }
    for (int idx = tid; idx < 4 * 128; idx += 256) cs[idx] = 0.f;
    __syncthreads();

    const int c0 = (tid & 7) * 2;          // gate-col pair
    const int b0 = (tid >> 3) * 4;         // batch quad

    for (int t = 0; t < T_; t++) {
        const float* hp = (t == 0) ? g_h0 : (g_hseq + (size_t)(t - 1) * U_ * B_);

        uint64_t acc[2][2];                // [b-pair][col]
        acc[0][0] = acc[0][1] = acc[1][0] = acc[1][1] = 0ull;

        // prefetch chunk 0 (contiguous 8192 floats)
        float4 pf[8];
#pragma unroll
        for (int i = 0; i < 8; i++)
            pf[i] = *reinterpret_cast<const float4*>(&hp[(size_t)(i * 256 + tid) * 4]);

        for (int kc = 0; kc < U_ / CHUNK; kc++) {
            float* bc = buf + (kc & 1) * (CHUNK * 128);
#pragma unroll
            for (int i = 0; i < 8; i++)
                *reinterpret_cast<float4*>(&bc[(i * 256 + tid) * 4]) = pf[i];
            __syncthreads();
            if (kc + 1 < U_ / CHUNK) {
                const float* hq = hp + (size_t)(kc + 1) * CHUNK * 128;
#pragma unroll
                for (int i = 0; i < 8; i++)
                    pf[i] = *reinterpret_cast<const float4*>(&hq[(size_t)(i * 256 + tid) * 4]);
            }
            const float* wb = Ws + kc * CHUNK * 16;
#pragma unroll
            for (int kk = 0; kk < CHUNK; kk++) {
                ulonglong2 h = *reinterpret_cast<ulonglong2*>(&bc[kk * 128 + b0]);
                float2 w = *reinterpret_cast<float2*>(
                    const_cast<float*>(&wb[kk * 16 + c0]));
                uint64_t w0 = splat2(w.x), w1 = splat2(w.y);
                ffma2(acc[0][0], h.x, w0);
                ffma2(acc[1][0], h.y, w0);
                ffma2(acc[0][1], h.x, w1);
                ffma2(acc[1][1], h.y, w1);
            }
        }

        // stash z into buf[0] region as [c(16)][b(128)]  (safe: see sync chain)
        float* stash = buf;
#pragma unroll
        for (int c = 0; c < 2; c++) {
            float2 v0 = unpack2(acc[0][c]);
            float2 v1 = unpack2(acc[1][c]);
            *reinterpret_cast<float2*>(&stash[(c0 + c) * 128 + b0])     = v0;
            *reinterpret_cast<float2*>(&stash[(c0 + c) * 128 + b0 + 2]) = v1;
        }
        __syncthreads();

        // gate epilogue: coalesced xz loads (g_xz is [t][c][b])
        const float* xz_t = g_xz + (size_t)t * G_ * B_;
        float* h_out = g_hseq + (size_t)t * U_ * B_;
#pragma unroll
        for (int r = 0; r < 2; r++) {
            int p = tid + r * 256;
            int b = p & 127, ul = p >> 7;
            int u = ublk + ul;
            float zi = stash[(0 * 4 + ul) * 128 + b] + xz_t[(size_t)(0 * U_ + u) * B_ + b];
            float zf = stash[(1 * 4 + ul) * 128 + b] + xz_t[(size_t)(1 * U_ + u) * B_ + b];
            float zg = stash[(2 * 4 + ul) * 128 + b] + xz_t[(size_t)(2 * U_ + u) * B_ + b];
            float zo = stash[(3 * 4 + ul) * 128 + b] + xz_t[(size_t)(3 * U_ + u) * B_ + b];
            float ig = 1.f / (1.f + __expf(-zi));
            float fg = 1.f / (1.f + __expf(-zf));
            float gg = 1.f - 2.f / (1.f + __expf(2.f * zg));
            float og = 1.f / (1.f + __expf(-zo));
            float cn = fg * cs[ul * 128 + b] + ig * gg;
            cs[ul * 128 + b] = cn;
            float th = 1.f - 2.f / (1.f + __expf(2.f * cn));
            h_out[(size_t)u * B_ + b] = og * th;
        }

        // software grid barrier
        __threadfence();
        __syncthreads();
        if (tid == 0) {
            atomicAdd(&g_bar, 1u);
            unsigned tgt = (unsigned)(NBLK * (t + 1));
            while (*((volatile unsigned*)&g_bar) < tgt) { }
            __threadfence();
        }
        __syncthreads();
    }
}

// ---------------------------------------------------------------------------
// GEMM 3: out[m, CODES] = relu(mask[m] * (h @ W_dense) + b_dense)
// A from g_hseq [t][u][b]; pack over cols (j)
// ---------------------------------------------------------------------------
__global__ __launch_bounds__(256)
void gemm_dense_kernel(const float* __restrict__ Bm,
                       const float* __restrict__ bias,
                       const float* __restrict__ mask,
                       float* __restrict__ C)
{
    __shared__ float As[16][128];
    __shared__ float Bs[16][128];

    const int tid = threadIdx.x;
    const int tx = tid & 15, ty = tid >> 4;
    const int tblk = blockIdx.y;
    const int col0 = blockIdx.x * 128;
    const float* Ablk = g_hseq + (size_t)tblk * U_ * B_;

    uint64_t acc[8][4];                    // [row][col-pair]
#pragma unroll
    for (int i = 0; i < 8; i++)
#pragma unroll
        for (int j = 0; j < 4; j++) acc[i][j] = 0ull;

    for (int k0 = 0; k0 < U_; k0 += 16) {
#pragma unroll
        for (int r = 0; r < 2; r++) {
            int e = tid + r * 256;
            int kk = e >> 5, b4 = (e & 31) << 2;
            *reinterpret_cast<float4*>(&As[kk][b4]) =
                *reinterpret_cast<const float4*>(&Ablk[(size_t)(k0 + kk) * B_ + b4]);
        }
#pragma unroll
        for (int r = 0; r < 2; r++) {
            int e = tid + r * 256;
            int kk = e >> 5, n4 = (e & 31) << 2;
            *reinterpret_cast<float4*>(&Bs[kk][n4]) =
                *reinterpret_cast<const float4*>(
                    &Bm[(size_t)(k0 + kk) * CODES_ + col0 + n4]);
        }
        __syncthreads();

#pragma unroll
        for (int kk = 0; kk < 16; kk++) {
            float a[8];
            *reinterpret_cast<float4*>(&a[0]) = *reinterpret_cast<float4*>(&As[kk][ty * 8]);
            *reinterpret_cast<float4*>(&a[4]) = *reinterpret_cast<float4*>(&As[kk][ty * 8 + 4]);
            uint64_t bp[4];
            ulonglong2 b01 = *reinterpret_cast<ulonglong2*>(&Bs[kk][tx * 8]);
            ulonglong2 b23 = *reinterpret_cast<ulonglong2*>(&Bs[kk][tx * 8 + 4]);
            bp[0] = b01.x; bp[1] = b01.y; bp[2] = b23.x; bp[3] = b23.y;
#pragma unroll
            for (int i = 0; i < 8; i++) {
                uint64_t as = splat2(a[i]);
                ffma2(acc[i][0], as, bp[0]);
                ffma2(acc[i][1], as, bp[1]);
                ffma2(acc[i][2], as, bp[2]);
                ffma2(acc[i][3], as, bp[3]);
            }
        }
        __syncthreads();
    }

    float bv[8];
#pragma unroll
    for (int j = 0; j < 8; j++) bv[j] = bias[col0 + tx * 8 + j];

#pragma unroll
    for (int i = 0; i < 8; i++) {
        int b = ty * 8 + i;
        size_t row = (size_t)tblk * 128 + b;
        float mk = mask[row];
        float2 p0 = unpack2(acc[i][0]);
        float2 p1 = unpack2(acc[i][1]);
        float2 p2 = unpack2(acc[i][2]);
        float2 p3 = unpack2(acc[i][3]);
        float4 v0, v1;
        v0.x = fmaxf(p0.x * mk + bv[0], 0.f);
        v0.y = fmaxf(p0.y * mk + bv[1], 0.f);
        v0.z = fmaxf(p1.x * mk + bv[2], 0.f);
        v0.w = fmaxf(p1.y * mk + bv[3], 0.f);
        v1.x = fmaxf(p2.x * mk + bv[4], 0.f);
        v1.y = fmaxf(p2.y * mk + bv[5], 0.f);
        v1.z = fmaxf(p3.x * mk + bv[6], 0.f);
        v1.w = fmaxf(p3.y * mk + bv[7], 0.f);
        *reinterpret_cast<float4*>(&C[row * CODES_ + col0 + tx * 8])     = v0;
        *reinterpret_cast<float4*>(&C[row * CODES_ + col0 + tx * 8 + 4]) = v1;
    }
}

// ---------------------------------------------------------------------------
__global__ __launch_bounds__(256)
void softmax_kernel(float* __restrict__ out)
{
    __shared__ float red[256];
    const int row = blockIdx.x;
    const int tid = threadIdx.x;
    float* p = out + (size_t)row * CODES_;

    float v[4];
    float m = -1e30f;
#pragma unroll
    for (int i = 0; i < 4; i++) {
        v[i] = p[tid + i * 256];
        m = fmaxf(m, v[i]);
    }
    red[tid] = m;
    __syncthreads();
    for (int s = 128; s > 0; s >>= 1) {
        if (tid < s) red[tid] = fmaxf(red[tid], red[tid + s]);
        __syncthreads();
    }
    m = red[0];
    __syncthreads();

    float sum = 0.f;
#pragma unroll
    for (int i = 0; i < 4; i++) {
        v[i] = __expf(v[i] - m);
        sum += v[i];
    }
    red[tid] = sum;
    __syncthreads();
    for (int s = 128; s > 0; s >>= 1) {
        if (tid < s) red[tid] += red[tid + s];
        __syncthreads();
    }
    float inv = 1.f / red[0];
#pragma unroll
    for (int i = 0; i < 4; i++) p[tid + i * 256] = v[i] * inv;
}

// ---------------------------------------------------------------------------
extern "C" void kernel_launch(void* const* d_in, const int* in_sizes, int n_in,
                              void* d_out, int out_size)
{
    const float* x       = (const float*)d_in[0];
    const float* mask    = (const float*)d_in[1];
    const float* W_in    = (const float*)d_in[2];
    const float* W_rec   = (const float*)d_in[3];
    const float* b_lstm  = (const float*)d_in[4];
    const float* W_dense = (const float*)d_in[5];
    const float* b_dense = (const float*)d_in[6];
    float* out = (float*)d_out;

    init_kernel<<<(U_ * B_ + 255) / 256, 256>>>();

    {   // xz = x @ W_in + b  (writes transposed [t][c][b])
        dim3 grid(G_ / 128, T_);
        gemm_xz_kernel<<<grid, 256>>>(x, W_in, b_lstm);
    }

    {   // recurrence: one persistent launch (98KB dynamic smem)
        const int smem = (512 * 16 + 2 * CHUNK * 128 + 4 * 128) * (int)sizeof(float);
        static int attr_set = 0;
        if (!attr_set) {
            cudaFuncSetAttribute(lstm_persistent_kernel,
                                 cudaFuncAttributeMaxDynamicSharedMemorySize, smem);
            attr_set = 1;
        }
        lstm_persistent_kernel<<<NBLK, 256, smem>>>(W_rec);
    }

    {   // dense + mask + relu
        dim3 grid(CODES_ / 128, T_);
        gemm_dense_kernel<<<grid, 256>>>(W_dense, b_dense, mask, out);
    }

    softmax_kernel<<<T_ * B_, 256>>>(out);
}

// round 4
// speedup vs baseline: 2.1726x; 1.0569x over previous
#include <cuda_runtime.h>
#include <math.h>
#include <stdint.h>

#define T_     256
#define B_     128
#define F_     1024
#define U_     512
#define G_     2048   // 4*U
#define CODES_ 1024
#define NBLK   128
#define UB     4
#define CHUNK  64

// Scratch (module-scope device allocations, permitted)
__device__ float g_xz[(size_t)T_ * G_ * B_];     // [t][c][b]  c = gate*512+u
__device__ float g_hseq[(size_t)T_ * U_ * B_];   // [t][u][b]
__device__ float g_h0[U_ * B_];
__device__ unsigned g_bar;

// ---------------------------------------------------------------------------
// helpers
// ---------------------------------------------------------------------------
__device__ __forceinline__ uint64_t splat2(float x) {
    uint64_t d; asm("mov.b64 %0, {%1, %1};" : "=l"(d) : "f"(x)); return d;
}
__device__ __forceinline__ void ffma2(uint64_t& d, uint64_t a, uint64_t b) {
    asm("fma.rn.f32x2 %0, %1, %2, %0;" : "+l"(d) : "l"(a), "l"(b));
}
__device__ __forceinline__ float2 unpack2(uint64_t d) {
    float2 r; asm("mov.b64 {%0, %1}, %2;" : "=f"(r.x), "=f"(r.y) : "l"(d)); return r;
}
__device__ __forceinline__ uint32_t f2t(float x) {
    uint32_t r; asm("cvt.rna.tf32.f32 %0, %1;" : "=r"(r) : "f"(x)); return r;
}
__device__ __forceinline__ void split4(float4 v, uint4& hi, uint4& lo) {
    hi.x = f2t(v.x); hi.y = f2t(v.y); hi.z = f2t(v.z); hi.w = f2t(v.w);
    lo.x = f2t(v.x - __uint_as_float(hi.x));
    lo.y = f2t(v.y - __uint_as_float(hi.y));
    lo.z = f2t(v.z - __uint_as_float(hi.z));
    lo.w = f2t(v.w - __uint_as_float(hi.w));
}
__device__ __forceinline__ void mma_tf32(float* d,
                                         const uint32_t* a, const uint32_t* b) {
    asm volatile("mma.sync.aligned.m16n8k8.row.col.f32.tf32.tf32.f32 "
        "{%0,%1,%2,%3}, {%4,%5,%6,%7}, {%8,%9}, {%0,%1,%2,%3};"
        : "+f"(d[0]), "+f"(d[1]), "+f"(d[2]), "+f"(d[3])
        : "r"(a[0]), "r"(a[1]), "r"(a[2]), "r"(a[3]), "r"(b[0]), "r"(b[1]));
}

// ---------------------------------------------------------------------------
__global__ void init_kernel() {
    int i = blockIdx.x * blockDim.x + threadIdx.x;
    if (i < U_ * B_) g_h0[i] = 0.f;
    if (i == 0) g_bar = 0u;
}

// ---------------------------------------------------------------------------
// GEMM 1 (tensor core, 3xTF32): xz = x @ W_in + b, output g_xz[t][col][b]
// block 512 thr (16 warps 4x4), BM=BN=128, BK=32, warp tile 32x32
// As [m=128][k=32] stride 36 (frag-gather conflict-free), Bs [k=32][n=128] stride 136
// ---------------------------------------------------------------------------
#define AS_STRIDE 36
#define BS_STRIDE 136

__global__ __launch_bounds__(512)
void gemm_xz_tc(const float* __restrict__ A,
                const float* __restrict__ Bm,
                const float* __restrict__ bias)
{
    extern __shared__ uint32_t smx[];
    uint32_t* AsH = smx;                       // 128*36
    uint32_t* AsL = AsH + 128 * AS_STRIDE;
    uint32_t* BsH = AsL + 128 * AS_STRIDE;     // 32*136
    uint32_t* BsL = BsH + 32 * BS_STRIDE;

    const int tid  = threadIdx.x;
    const int lane = tid & 31, w = tid >> 5;
    const int gid  = lane >> 2, tig = lane & 3;
    const int wm   = (w >> 2) * 32, wn = (w & 3) * 32;
    const int t    = blockIdx.y;
    const int row0 = t * 128;
    const int col0 = blockIdx.x * 128;

    float C[2][4][4];
#pragma unroll
    for (int im = 0; im < 2; im++)
#pragma unroll
        for (int in = 0; in < 4; in++)
#pragma unroll
            for (int r = 0; r < 4; r++) C[im][in][r] = 0.f;

    for (int k0 = 0; k0 < F_; k0 += 32) {
#pragma unroll
        for (int r = 0; r < 2; r++) {           // A: 128x32
            int e = tid + r * 512;
            int row = e >> 3, k4 = (e & 7) << 2;
            float4 v = *reinterpret_cast<const float4*>(
                &A[(size_t)(row0 + row) * F_ + k0 + k4]);
            uint4 hi, lo; split4(v, hi, lo);
            *reinterpret_cast<uint4*>(&AsH[row * AS_STRIDE + k4]) = hi;
            *reinterpret_cast<uint4*>(&AsL[row * AS_STRIDE + k4]) = lo;
        }
#pragma unroll
        for (int r = 0; r < 2; r++) {           // B: 32x128
            int e = tid + r * 512;
            int kk = e >> 5, n4 = (e & 31) << 2;
            float4 v = *reinterpret_cast<const float4*>(
                &Bm[(size_t)(k0 + kk) * G_ + col0 + n4]);
            uint4 hi, lo; split4(v, hi, lo);
            *reinterpret_cast<uint4*>(&BsH[kk * BS_STRIDE + n4]) = hi;
            *reinterpret_cast<uint4*>(&BsL[kk * BS_STRIDE + n4]) = lo;
        }
        __syncthreads();

#pragma unroll
        for (int k8 = 0; k8 < 4; k8++) {
            uint32_t aH[2][4], aL[2][4], bH[4][2], bL[4][2];
#pragma unroll
            for (int im = 0; im < 2; im++) {
                int m = wm + im * 16;
                int p0 = (m + gid) * AS_STRIDE + k8 * 8 + tig;
                int p1 = (m + gid + 8) * AS_STRIDE + k8 * 8 + tig;
                aH[im][0] = AsH[p0];     aH[im][1] = AsH[p1];
                aH[im][2] = AsH[p0 + 4]; aH[im][3] = AsH[p1 + 4];
                aL[im][0] = AsL[p0];     aL[im][1] = AsL[p1];
                aL[im][2] = AsL[p0 + 4]; aL[im][3] = AsL[p1 + 4];
            }
#pragma unroll
            for (int in = 0; in < 4; in++) {
                int n = wn + in * 8 + gid;
                int kb = k8 * 8 + tig;
                bH[in][0] = BsH[kb * BS_STRIDE + n];
                bH[in][1] = BsH[(kb + 4) * BS_STRIDE + n];
                bL[in][0] = BsL[kb * BS_STRIDE + n];
                bL[in][1] = BsL[(kb + 4) * BS_STRIDE + n];
            }
#pragma unroll
            for (int im = 0; im < 2; im++)
#pragma unroll
                for (int in = 0; in < 4; in++) {
                    mma_tf32(C[im][in], aH[im], bH[in]);
                    mma_tf32(C[im][in], aL[im], bH[in]);
                    mma_tf32(C[im][in], aH[im], bL[in]);
                }
        }
        __syncthreads();
    }

    // transposed epilogue: g_xz[t][n][b]
#pragma unroll
    for (int im = 0; im < 2; im++) {
        int b = wm + im * 16 + gid;
#pragma unroll
        for (int in = 0; in < 4; in++) {
            int n = col0 + wn + in * 8 + 2 * tig;
            float bz0 = bias[n], bz1 = bias[n + 1];
            size_t p = ((size_t)t * G_ + n) * B_;
            g_xz[p + b]           = C[im][in][0] + bz0;
            g_xz[p + B_ + b]      = C[im][in][1] + bz1;
            g_xz[p + b + 8]       = C[im][in][2] + bz0;
            g_xz[p + B_ + b + 8]  = C[im][in][3] + bz1;
        }
    }
}

// ---------------------------------------------------------------------------
// GEMM 3 (tensor core, 3xTF32): out = relu(mask * (h @ W_dense) + b_dense)
// A from g_hseq [t][u][b] (k-major): As kept [k=32][b=128] stride 136
// ---------------------------------------------------------------------------
__global__ __launch_bounds__(512)
void gemm_dense_tc(const float* __restrict__ Bm,
                   const float* __restrict__ bias,
                   const float* __restrict__ mask,
                   float* __restrict__ Cout)
{
    extern __shared__ uint32_t smx[];
    uint32_t* AsH = smx;                       // [k=32][b=128] stride 136
    uint32_t* AsL = AsH + 32 * BS_STRIDE;
    uint32_t* BsH = AsL + 32 * BS_STRIDE;      // [k=32][n=128] stride 136
    uint32_t* BsL = BsH + 32 * BS_STRIDE;

    const int tid  = threadIdx.x;
    const int lane = tid & 31, w = tid >> 5;
    const int gid  = lane >> 2, tig = lane & 3;
    const int wm   = (w >> 2) * 32, wn = (w & 3) * 32;
    const int t    = blockIdx.y;
    const int col0 = blockIdx.x * 128;
    const float* Ablk = g_hseq + (size_t)t * U_ * B_;

    float C[2][4][4];
#pragma unroll
    for (int im = 0; im < 2; im++)
#pragma unroll
        for (int in = 0; in < 4; in++)
#pragma unroll
            for (int r = 0; r < 4; r++) C[im][in][r] = 0.f;

    for (int k0 = 0; k0 < U_; k0 += 32) {
#pragma unroll
        for (int r = 0; r < 2; r++) {           // A: [k][b] natural
            int e = tid + r * 512;
            int kk = e >> 5, b4 = (e & 31) << 2;
            float4 v = *reinterpret_cast<const float4*>(
                &Ablk[(size_t)(k0 + kk) * B_ + b4]);
            uint4 hi, lo; split4(v, hi, lo);
            *reinterpret_cast<uint4*>(&AsH[kk * BS_STRIDE + b4]) = hi;
            *reinterpret_cast<uint4*>(&AsL[kk * BS_STRIDE + b4]) = lo;
        }
#pragma unroll
        for (int r = 0; r < 2; r++) {           // B: [k][n]
            int e = tid + r * 512;
            int kk = e >> 5, n4 = (e & 31) << 2;
            float4 v = *reinterpret_cast<const float4*>(
                &Bm[(size_t)(k0 + kk) * CODES_ + col0 + n4]);
            uint4 hi, lo; split4(v, hi, lo);
            *reinterpret_cast<uint4*>(&BsH[kk * BS_STRIDE + n4]) = hi;
            *reinterpret_cast<uint4*>(&BsL[kk * BS_STRIDE + n4]) = lo;
        }
        __syncthreads();

#pragma unroll
        for (int k8 = 0; k8 < 4; k8++) {
            uint32_t aH[2][4], aL[2][4], bH[4][2], bL[4][2];
#pragma unroll
            for (int im = 0; im < 2; im++) {
                int m = wm + im * 16 + gid;       // batch row
                int kb = k8 * 8 + tig;
                int p0 = kb * BS_STRIDE + m;
                aH[im][0] = AsH[p0];      aH[im][1] = AsH[p0 + 8];
                aH[im][2] = AsH[p0 + 4 * BS_STRIDE];
                aH[im][3] = AsH[p0 + 4 * BS_STRIDE + 8];
                aL[im][0] = AsL[p0];      aL[im][1] = AsL[p0 + 8];
                aL[im][2] = AsL[p0 + 4 * BS_STRIDE];
                aL[im][3] = AsL[p0 + 4 * BS_STRIDE + 8];
            }
#pragma unroll
            for (int in = 0; in < 4; in++) {
                int n = wn + in * 8 + gid;
                int kb = k8 * 8 + tig;
                bH[in][0] = BsH[kb * BS_STRIDE + n];
                bH[in][1] = BsH[(kb + 4) * BS_STRIDE + n];
                bL[in][0] = BsL[kb * BS_STRIDE + n];
                bL[in][1] = BsL[(kb + 4) * BS_STRIDE + n];
            }
#pragma unroll
            for (int im = 0; im < 2; im++)
#pragma unroll
                for (int in = 0; in < 4; in++) {
                    mma_tf32(C[im][in], aH[im], bH[in]);
                    mma_tf32(C[im][in], aL[im], bH[in]);
                    mma_tf32(C[im][in], aH[im], bL[in]);
                }
        }
        __syncthreads();
    }

#pragma unroll
    for (int im = 0; im < 2; im++) {
        int b = wm + im * 16 + gid;
        int r0 = t * 128 + b, r1 = r0 + 8;
        float m0 = mask[r0], m1 = mask[r1];
#pragma unroll
        for (int in = 0; in < 4; in++) {
            int n = col0 + wn + in * 8 + 2 * tig;
            float bz0 = bias[n], bz1 = bias[n + 1];
            Cout[(size_t)r0 * CODES_ + n]     = fmaxf(C[im][in][0] * m0 + bz0, 0.f);
            Cout[(size_t)r0 * CODES_ + n + 1] = fmaxf(C[im][in][1] * m0 + bz1, 0.f);
            Cout[(size_t)r1 * CODES_ + n]     = fmaxf(C[im][in][2] * m1 + bz0, 0.f);
            Cout[(size_t)r1 * CODES_ + n + 1] = fmaxf(C[im][in][3] * m1 + bz1, 0.f);
        }
    }
}

// ---------------------------------------------------------------------------
// Persistent LSTM (unchanged from R3)
// ---------------------------------------------------------------------------
__global__ __launch_bounds__(256)
void lstm_persistent_kernel(const float* __restrict__ W_rec)
{
    extern __shared__ float sm[];
    float* Ws  = sm;
    float* buf = sm + 512 * 16;
    float* cs  = buf + 2 * CHUNK * 128;

    const int tid  = threadIdx.x;
    const int ublk = blockIdx.x * UB;

    for (int idx = tid; idx < 512 * 16; idx += 256) {
        int k = idx >> 4, c = idx & 15;
        Ws[idx] = W_rec[(size_t)k * G_ + (c >> 2) * U_ + ublk + (c & 3)];
    }
    for (int idx = tid; idx < 4 * 128; idx += 256) cs[idx] = 0.f;
    __syncthreads();

    const int c0 = (tid & 7) * 2;
    const int b0 = (tid >> 3) * 4;

    for (int t = 0; t < T_; t++) {
        const float* hp = (t == 0) ? g_h0 : (g_hseq + (size_t)(t - 1) * U_ * B_);

        uint64_t acc[2][2];
        acc[0][0] = acc[0][1] = acc[1][0] = acc[1][1] = 0ull;

        float4 pf[8];
#pragma unroll
        for (int i = 0; i < 8; i++)
            pf[i] = *reinterpret_cast<const float4*>(&hp[(size_t)(i * 256 + tid) * 4]);

        for (int kc = 0; kc < U_ / CHUNK; kc++) {
            float* bc = buf + (kc & 1) * (CHUNK * 128);
#pragma unroll
            for (int i = 0; i < 8; i++)
                *reinterpret_cast<float4*>(&bc[(i * 256 + tid) * 4]) = pf[i];
            __syncthreads();
            if (kc + 1 < U_ / CHUNK) {
                const float* hq = hp + (size_t)(kc + 1) * CHUNK * 128;
#pragma unroll
                for (int i = 0; i < 8; i++)
                    pf[i] = *reinterpret_cast<const float4*>(&hq[(size_t)(i * 256 + tid) * 4]);
            }
            const float* wb = Ws + kc * CHUNK * 16;
#pragma unroll
            for (int kk = 0; kk < CHUNK; kk++) {
                ulonglong2 h = *reinterpret_cast<ulonglong2*>(&bc[kk * 128 + b0]);
                float2 w = *reinterpret_cast<float2*>(
                    const_cast<float*>(&wb[kk * 16 + c0]));
                uint64_t w0 = splat2(w.x), w1 = splat2(w.y);
                ffma2(acc[0][0], h.x, w0);
                ffma2(acc[1][0], h.y, w0);
                ffma2(acc[0][1], h.x, w1);
                ffma2(acc[1][1], h.y, w1);
            }
        }

        float* stash = buf;
#pragma unroll
        for (int c = 0; c < 2; c++) {
            float2 v0 = unpack2(acc[0][c]);
            float2 v1 = unpack2(acc[1][c]);
            *reinterpret_cast<float2*>(&stash[(c0 + c) * 128 + b0])     = v0;
            *reinterpret_cast<float2*>(&stash[(c0 + c) * 128 + b0 + 2]) = v1;
        }
        __syncthreads();

        const float* xz_t = g_xz + (size_t)t * G_ * B_;
        float* h_out = g_hseq + (size_t)t * U_ * B_;
#pragma unroll
        for (int r = 0; r < 2; r++) {
            int p = tid + r * 256;
            int b = p & 127, ul = p >> 7;
            int u = ublk + ul;
            float zi = stash[(0 * 4 + ul) * 128 + b] + xz_t[(size_t)(0 * U_ + u) * B_ + b];
            float zf = stash[(1 * 4 + ul) * 128 + b] + xz_t[(size_t)(1 * U_ + u) * B_ + b];
            float zg = stash[(2 * 4 + ul) * 128 + b] + xz_t[(size_t)(2 * U_ + u) * B_ + b];
            float zo = stash[(3 * 4 + ul) * 128 + b] + xz_t[(size_t)(3 * U_ + u) * B_ + b];
            float ig = 1.f / (1.f + __expf(-zi));
            float fg = 1.f / (1.f + __expf(-zf));
            float gg = 1.f - 2.f / (1.f + __expf(2.f * zg));
            float og = 1.f / (1.f + __expf(-zo));
            float cn = fg * cs[ul * 128 + b] + ig * gg;
            cs[ul * 128 + b] = cn;
            float th = 1.f - 2.f / (1.f + __expf(2.f * cn));
            h_out[(size_t)u * B_ + b] = og * th;
        }

        __threadfence();
        __syncthreads();
        if (tid == 0) {
            atomicAdd(&g_bar, 1u);
            unsigned tgt = (unsigned)(NBLK * (t + 1));
            while (*((volatile unsigned*)&g_bar) < tgt) { }
            __threadfence();
        }
        __syncthreads();
    }
}

// ---------------------------------------------------------------------------
__global__ __launch_bounds__(256)
void softmax_kernel(float* __restrict__ out)
{
    __shared__ float red[256];
    const int row = blockIdx.x;
    const int tid = threadIdx.x;
    float* p = out + (size_t)row * CODES_;

    float v[4];
    float m = -1e30f;
#pragma unroll
    for (int i = 0; i < 4; i++) {
        v[i] = p[tid + i * 256];
        m = fmaxf(m, v[i]);
    }
    red[tid] = m;
    __syncthreads();
    for (int s = 128; s > 0; s >>= 1) {
        if (tid < s) red[tid] = fmaxf(red[tid], red[tid + s]);
        __syncthreads();
    }
    m = red[0];
    __syncthreads();

    float sum = 0.f;
#pragma unroll
    for (int i = 0; i < 4; i++) {
        v[i] = __expf(v[i] - m);
        sum += v[i];
    }
    red[tid] = sum;
    __syncthreads();
    for (int s = 128; s > 0; s >>= 1) {
        if (tid < s) red[tid] += red[tid + s];
        __syncthreads();
    }
    float inv = 1.f / red[0];
#pragma unroll
    for (int i = 0; i < 4; i++) p[tid + i * 256] = v[i] * inv;
}

// ---------------------------------------------------------------------------
extern "C" void kernel_launch(void* const* d_in, const int* in_sizes, int n_in,
                              void* d_out, int out_size)
{
    const float* x       = (const float*)d_in[0];
    const float* mask    = (const float*)d_in[1];
    const float* W_in    = (const float*)d_in[2];
    const float* W_rec   = (const float*)d_in[3];
    const float* b_lstm  = (const float*)d_in[4];
    const float* W_dense = (const float*)d_in[5];
    const float* b_dense = (const float*)d_in[6];
    float* out = (float*)d_out;

    const int smem_xz    = (2 * 128 * AS_STRIDE + 2 * 32 * BS_STRIDE) * 4;
    const int smem_dense = (4 * 32 * BS_STRIDE) * 4;
    const int smem_lstm  = (512 * 16 + 2 * CHUNK * 128 + 4 * 128) * (int)sizeof(float);
    static int attr_set = 0;
    if (!attr_set) {
        cudaFuncSetAttribute(gemm_xz_tc,
                             cudaFuncAttributeMaxDynamicSharedMemorySize, smem_xz);
        cudaFuncSetAttribute(gemm_dense_tc,
                             cudaFuncAttributeMaxDynamicSharedMemorySize, smem_dense);
        cudaFuncSetAttribute(lstm_persistent_kernel,
                             cudaFuncAttributeMaxDynamicSharedMemorySize, smem_lstm);
        attr_set = 1;
    }

    init_kernel<<<(U_ * B_ + 255) / 256, 256>>>();

    {   // xz = x @ W_in + b  (tensor core 3xTF32, transposed output)
        dim3 grid(G_ / 128, T_);
        gemm_xz_tc<<<grid, 512, smem_xz>>>(x, W_in, b_lstm);
    }

    lstm_persistent_kernel<<<NBLK, 256, smem_lstm>>>(W_rec);

    {   // dense + mask + relu (tensor core 3xTF32)
        dim3 grid(CODES_ / 128, T_);
        gemm_dense_tc<<<grid, 512, smem_dense>>>(W_dense, b_dense, mask, out);
    }

    softmax_kernel<<<T_ * B_, 256>>>(out);
}